// round 11
// baseline (speedup 1.0000x reference)
#include <cuda_runtime.h>
#include <cuda_fp16.h>
#include <cuda_bf16.h>

#define Nn   100000
#define Ee   1600000
#define FIN  128
#define FHID 32
#define FOUT 2

// ---------------- scratch (__device__ globals; no allocation) ----------------
// g_cnt / g_bar rely on zero-init at module load; g_cnt is re-zeroed in the
// final phase each call; g_bar is a monotonic barrier counter (round-up logic
// makes it self-consistent across calls/replays).
__device__ __align__(16) __half g_g1h[Nn * FHID];   // dinv-scaled h1 (fp16)
__device__ __align__(16) __half g_agg1h[Nn * FHID]; // layer-1 accum (fp16)
__device__ __align__(8)  float g_g2[Nn * FOUT];     // dinv-scaled h2
__device__ __align__(8)  float g_agg2[Nn * FOUT];   // layer-2 accum
__device__ int g_cnt[Nn];                            // in-degree (no self loop)
__device__ unsigned g_bar;                           // grid barrier counter

// grid-wide barrier: arrive (release) + spin to next multiple of nblocks
__device__ __forceinline__ void gridbar(int nb) {
    __syncthreads();
    if (threadIdx.x == 0) {
        __threadfence();
        unsigned arrival = atomicAdd(&g_bar, 1u) + 1u;
        unsigned target  = ((arrival + (unsigned)nb - 1u) / (unsigned)nb) * (unsigned)nb;
        while (atomicAdd(&g_bar, 0u) < target) __nanosleep(64);
        __threadfence();
    }
    __syncthreads();
}

__global__ void __launch_bounds__(256) k_fused(
    const float* __restrict__ x,  const int* __restrict__ ei,
    const float* __restrict__ W1, const float* __restrict__ b1,
    const float* __restrict__ W2, const float* __restrict__ b2,
    float* __restrict__ out, int nblocks)
{
    __shared__ __align__(16) float sWp[FIN * FHID]; // 16 KB paired W1
    __shared__ __align__(16) float sx[64 * FIN];    // 32 KB x-rows (aliased in P3)
    const int tid = threadIdx.x;
    const int gt  = blockIdx.x * 256 + tid;
    const int GT  = nblocks * 256;

    // ---- P0: degree histogram (int4 vectorized) ----
    for (int t = gt; t < Ee / 4; t += GT) {
        int4 c = reinterpret_cast<const int4*>(ei + Ee)[t];
        atomicAdd(&g_cnt[c.x], 1);
        atomicAdd(&g_cnt[c.y], 1);
        atomicAdd(&g_cnt[c.z], 1);
        atomicAdd(&g_cnt[c.w], 1);
    }
    gridbar(nblocks);

    // ---- P1: g1 = dinv*(x@W1) via fma.rn.f32x2; fp16 store + agg1 self-loop init ----
    for (int i = tid; i < FIN * FHID; i += 256) {
        int k = i >> 5, lane = i & 31;
        sWp[(((k >> 1) * 32) + lane) * 2 + (k & 1)] = W1[i];
    }
    for (int tile = blockIdx.x; tile < (Nn + 63) / 64; tile += nblocks) {
        __syncthreads();                       // protect sx reuse (also fences sWp 1st iter)
        int nodeBase = tile * 64;
        {
            const float4* x4 = reinterpret_cast<const float4*>(x);
            float4* sx4 = reinterpret_cast<float4*>(sx);
            for (int i = tid; i < 2048; i += 256) {
                int node = nodeBase + (i >> 5);
                sx4[i] = (node < Nn) ? x4[(size_t)node * 32 + (i & 31)]
                                     : make_float4(0.f, 0.f, 0.f, 0.f);
            }
        }
        __syncthreads();

        int w = tid >> 5, lane = tid & 31;
        int n0 = w * 8;
        const ulonglong2* sxq = reinterpret_cast<const ulonglong2*>(sx);     // 32 per row
        const unsigned long long* sWq = reinterpret_cast<const unsigned long long*>(sWp);
        unsigned long long acc[8];
#pragma unroll
        for (int i = 0; i < 8; i++) acc[i] = 0ULL;
#pragma unroll
        for (int kp2 = 0; kp2 < 32; kp2++) {
            unsigned long long w0 = sWq[(2 * kp2 + 0) * 32 + lane];
            unsigned long long w1 = sWq[(2 * kp2 + 1) * 32 + lane];
#pragma unroll
            for (int i = 0; i < 8; i++) {
                ulonglong2 xv = sxq[(n0 + i) * 32 + kp2];
                asm("fma.rn.f32x2 %0, %1, %2, %0;" : "+l"(acc[i]) : "l"(xv.x), "l"(w0));
                asm("fma.rn.f32x2 %0, %1, %2, %0;" : "+l"(acc[i]) : "l"(xv.y), "l"(w1));
            }
        }
#pragma unroll
        for (int i = 0; i < 8; i++) {
            int gn = nodeBase + n0 + i;
            if (gn < Nn) {
                float lo, hi;
                asm("mov.b64 {%0,%1}, %2;" : "=f"(lo), "=f"(hi) : "l"(acc[i]));
                float dinv = rsqrtf((float)g_cnt[gn] + 1.0f);
                __half h = __float2half_rn(dinv * (lo + hi));
                g_g1h  [gn * FHID + lane] = h;
                g_agg1h[gn * FHID + lane] = h;
            }
        }
    }
    gridbar(nblocks);

    // ---- P2: layer-1 edge scatter (fp16 v4.f16x2 RED), 4 units/iter for MLP ----
    {
        const unsigned total = (unsigned)Ee * 4u;
        const unsigned S = (unsigned)GT;
        unsigned t = (unsigned)gt;
        for (; t + 3u * S < total; t += 4u * S) {
#pragma unroll
            for (int u = 0; u < 4; u++) {
                unsigned tt = t + (unsigned)u * S;
                int e = tt >> 2, j = tt & 3;
                int r = ei[e], c = ei[Ee + e];
                uint4 v = reinterpret_cast<const uint4*>(g_g1h)[r * 4 + j];
                __half* dst = g_agg1h + c * FHID + j * 8;
                asm volatile("red.global.add.noftz.v4.f16x2 [%0], {%1,%2,%3,%4};"
                             :: "l"(dst), "r"(v.x), "r"(v.y), "r"(v.z), "r"(v.w) : "memory");
            }
        }
        for (; t < total; t += S) {
            int e = t >> 2, j = t & 3;
            int r = ei[e], c = ei[Ee + e];
            uint4 v = reinterpret_cast<const uint4*>(g_g1h)[r * 4 + j];
            __half* dst = g_agg1h + c * FHID + j * 8;
            asm volatile("red.global.add.noftz.v4.f16x2 [%0], {%1,%2,%3,%4};"
                         :: "l"(dst), "r"(v.x), "r"(v.y), "r"(v.z), "r"(v.w) : "memory");
        }
    }
    gridbar(nblocks);

    // ---- P3: layer2 thread-per-node (W2/b1 staged in sx) ----
    if (tid < FHID * FOUT) sx[tid] = W2[tid];
    if (tid < FHID)        sx[64 + tid] = b1[tid];
    __syncthreads();
    for (int n = gt; n < Nn; n += GT) {
        float dinv = rsqrtf((float)g_cnt[n] + 1.0f);
        const uint4* row = reinterpret_cast<const uint4*>(g_agg1h) + n * 4;
        float p0 = 0.f, p1 = 0.f;
#pragma unroll
        for (int q = 0; q < 4; q++) {
            uint4 v = row[q];
            unsigned u[4] = {v.x, v.y, v.z, v.w};
#pragma unroll
            for (int h = 0; h < 4; h++) {
                float2 f = __half22float2(*reinterpret_cast<const __half2*>(&u[h]));
                int k = q * 8 + h * 2;
                float a0 = fmaxf(fmaf(dinv, f.x, sx[64 + k]), 0.f);
                float a1 = fmaxf(fmaf(dinv, f.y, sx[64 + k + 1]), 0.f);
                p0 = fmaf(a0, sx[2 * k + 0], fmaf(a1, sx[2 * k + 2], p0));
                p1 = fmaf(a0, sx[2 * k + 1], fmaf(a1, sx[2 * k + 3], p1));
            }
        }
        float2 g = make_float2(dinv * p0, dinv * p1);
        reinterpret_cast<float2*>(g_g2)[n]   = g;
        reinterpret_cast<float2*>(g_agg2)[n] = g;
    }
    gridbar(nblocks);

    // ---- P4: layer-2 edge scatter (fp32 float2 RED, 2 edges/iter) ----
    for (int t = gt; t < Ee / 2; t += GT) {
        int2 r = reinterpret_cast<const int2*>(ei)[t];
        int2 c = reinterpret_cast<const int2*>(ei + Ee)[t];
        float2 v0 = reinterpret_cast<const float2*>(g_g2)[r.x];
        float2 v1 = reinterpret_cast<const float2*>(g_g2)[r.y];
        atomicAdd(reinterpret_cast<float2*>(g_agg2) + c.x, v0);
        atomicAdd(reinterpret_cast<float2*>(g_agg2) + c.y, v1);
    }
    gridbar(nblocks);

    // ---- P5: finalize + log_softmax + reset g_cnt ----
    for (int n = gt; n < Nn; n += GT) {
        float dinv = rsqrtf((float)g_cnt[n] + 1.0f);
        float2 s = reinterpret_cast<const float2*>(g_agg2)[n];
        float o0 = dinv * s.x + b2[0];
        float o1 = dinv * s.y + b2[1];
        float m = fmaxf(o0, o1);
        float lse = m + logf(expf(o0 - m) + expf(o1 - m));
        reinterpret_cast<float2*>(out)[n] = make_float2(o0 - lse, o1 - lse);
        g_cnt[n] = 0;
    }
}

// ---------------- launch ----------------
extern "C" void kernel_launch(void* const* d_in, const int* in_sizes, int n_in,
                              void* d_out, int out_size) {
    const float* x  = (const float*)d_in[0];
    const int*   ei = (const int*)d_in[1];   // int32 on the wire
    const float* W1 = (const float*)d_in[2];
    const float* b1 = (const float*)d_in[3];
    const float* W2 = (const float*)d_in[4];
    const float* b2 = (const float*)d_in[5];
    float* out = (float*)d_out;

    int dev = 0; cudaGetDevice(&dev);
    int nsm = 148;
    cudaDeviceGetAttribute(&nsm, cudaDevAttrMultiProcessorCount, dev);
    int occ = 1;
    cudaOccupancyMaxActiveBlocksPerMultiprocessor(&occ, k_fused, 256, 0);
    if (occ < 1) occ = 1;
    int blocks = nsm * occ;                  // guaranteed co-resident

    k_fused<<<blocks, 256>>>(x, ei, W1, b1, W2, b2, out, blocks);
}